// round 1
// baseline (speedup 1.0000x reference)
#include <cuda_runtime.h>
#include <cstdint>

// ---------------------------------------------------------------------------
// SinkhornDistance: reference loop never runs, so
//   out[b] = sum_{i,j} c_{ij} * exp(-c_{ij}/EPS),
//   c_{ij} = (xs_i - ys_j)^2 + (x_i - y_j)^2,  EPS = 0.1
// B=8, N=M=4096.
// Compute-bound: 134M pairs, 1 MUFU.EX2 each -> MUFU-pipe floor ~28us.
// Strategy: f32x2 packed math for cost, scalar EX2, register-resident y tiles.
// ---------------------------------------------------------------------------

#define PACK2(out, lo, hi)  asm("mov.b64 %0, {%1, %2};" : "=l"(out) : "f"(lo), "f"(hi))
#define UNPACK2(lo, hi, in) asm("mov.b64 {%0, %1}, %2;" : "=f"(lo), "=f"(hi) : "l"(in))
#define ADD2(out, a, b)     asm("add.rn.f32x2 %0, %1, %2;" : "=l"(out) : "l"(a), "l"(b))
#define MUL2(out, a, b)     asm("mul.rn.f32x2 %0, %1, %2;" : "=l"(out) : "l"(a), "l"(b))
#define FMA2(out, a, b, c)  asm("fma.rn.f32x2 %0, %1, %2, %3;" : "=l"(out) : "l"(a), "l"(b), "l"(c))

static __device__ __forceinline__ float ex2f(float v) {
    float r;
    asm("ex2.approx.ftz.f32 %0, %1;" : "=f"(r) : "f"(v));
    return r;
}

static constexpr int B_   = 8;
static constexpr int N_   = 4096;
static constexpr int M_   = 4096;
static constexpr int TPB  = 256;   // threads per block
static constexpr int JPT  = 16;    // j columns per thread; TPB*JPT == M
static constexpr int ROWS = 32;    // i rows per block
static constexpr int BLK_PER_B = N_ / ROWS;  // 128 blocks per batch

// exp(-c/0.1) = exp2(c * (-10 * log2(e)))
static constexpr float NEG_K = -14.4269504088896341f;

__global__ void __launch_bounds__(TPB)
sinkhorn_kernel(const float* __restrict__ x,  const float* __restrict__ y,
                const float* __restrict__ xs, const float* __restrict__ ys,
                float* __restrict__ out)
{
    const int b  = blockIdx.x / BLK_PER_B;
    const int i0 = (blockIdx.x % BLK_PER_B) * ROWS;
    const int t  = threadIdx.x;
    const int jb = t * JPT;

    // Load this thread's 16 (y, ys) columns once; store NEGATED and packed
    // as f32x2 so the inner loop's subtraction becomes a packed add.
    const float4* y4  = reinterpret_cast<const float4*>(y  + (size_t)b * M_ + jb);
    const float4* ys4 = reinterpret_cast<const float4*>(ys + (size_t)b * M_ + jb);

    unsigned long long ny[JPT / 2], nys[JPT / 2];
#pragma unroll
    for (int q = 0; q < JPT / 4; q++) {
        float4 a = y4[q];
        float4 s = ys4[q];
        PACK2(ny[2 * q],      -a.x, -a.y);
        PACK2(ny[2 * q + 1],  -a.z, -a.w);
        PACK2(nys[2 * q],     -s.x, -s.y);
        PACK2(nys[2 * q + 1], -s.z, -s.w);
    }

    unsigned long long K2;
    PACK2(K2, NEG_K, NEG_K);

    const float* xrow  = x  + (size_t)b * N_ + i0;
    const float* xsrow = xs + (size_t)b * N_ + i0;

    float acc0 = 0.0f, acc1 = 0.0f;  // two accumulators to break FFMA chains

#pragma unroll 1
    for (int r = 0; r < ROWS; r++) {
        const float xi  = __ldg(xrow + r);    // uniform across warp -> broadcast
        const float xsi = __ldg(xsrow + r);
        unsigned long long xi2, xsi2;
        PACK2(xi2,  xi,  xi);
        PACK2(xsi2, xsi, xsi);

#pragma unroll
        for (int k = 0; k < JPT / 2; k++) {
            unsigned long long d1, d2, sq, c, tt;
            ADD2(d1, xsi2, nys[k]);          // xs_i - ys_j  (x2)
            ADD2(d2, xi2,  ny[k]);           // x_i  - y_j   (x2)
            MUL2(sq, d1, d1);                // d1^2
            FMA2(c,  d2, d2, sq);            // cost = d1^2 + d2^2
            MUL2(tt, c,  K2);                // cost * (-10*log2 e)
            float t0, t1, c0, c1;
            UNPACK2(t0, t1, tt);
            UNPACK2(c0, c1, c);
            acc0 = fmaf(c0, ex2f(t0), acc0); // += cost * exp(-cost/eps)
            acc1 = fmaf(c1, ex2f(t1), acc1);
        }
    }

    float acc = acc0 + acc1;

    // Warp reduction
#pragma unroll
    for (int off = 16; off > 0; off >>= 1)
        acc += __shfl_xor_sync(0xffffffffu, acc, off);

    __shared__ float wsum[TPB / 32];
    if ((t & 31) == 0) wsum[t >> 5] = acc;
    __syncthreads();

    if (t < TPB / 32) {
        float v = wsum[t];
#pragma unroll
        for (int off = TPB / 64; off > 0; off >>= 1)
            v += __shfl_xor_sync(0x000000ffu, v, off);
        if (t == 0) atomicAdd(out + b, v);
    }
}

__global__ void zero_kernel(float* out, int n) {
    int i = blockIdx.x * blockDim.x + threadIdx.x;
    if (i < n) out[i] = 0.0f;
}

extern "C" void kernel_launch(void* const* d_in, const int* in_sizes, int n_in,
                              void* d_out, int out_size)
{
    const float* x  = (const float*)d_in[0];  // x         [8,4096]
    const float* y  = (const float*)d_in[1];  // y         [8,4096]
    const float* xs = (const float*)d_in[2];  // x_support [8,4096]
    const float* ys = (const float*)d_in[3];  // y_support [8,4096]
    float* out = (float*)d_out;               // [8]

    (void)in_sizes; (void)n_in;

    zero_kernel<<<1, 32>>>(out, out_size);
    sinkhorn_kernel<<<B_ * BLK_PER_B, TPB>>>(x, y, xs, ys, out);
}